// round 4
// baseline (speedup 1.0000x reference)
#include <cuda_runtime.h>

#define NNODES 50000
#define NEDGES 800000
#define DIM 64
#define NSTEPS 5

typedef unsigned long long ull;

// Scratch state (allocation-free: __device__ globals), 16B-aligned for
// float4 loads and red.global.add.v4.f32.
__device__ __align__(16) float g_m[NNODES * DIM];     // messages m = h @ W
__device__ __align__(16) float g_agg[NNODES * DIM];   // scatter-add accumulator
__device__ __align__(16) float g_h[NNODES * DIM];     // hidden state ping buffer

// ---------- packed f32x2 helpers (ptxas never auto-fuses these) ----------
__device__ __forceinline__ ull pack2(float lo, float hi) {
    ull r; asm("mov.b64 %0, {%1, %2};" : "=l"(r) : "f"(lo), "f"(hi)); return r;
}
__device__ __forceinline__ void fma2(ull& d, ull a, ull b) {
    asm("fma.rn.f32x2 %0, %1, %2, %0;" : "+l"(d) : "l"(a), "l"(b));
}
__device__ __forceinline__ float2 unpack2(ull v) {
    float2 r; asm("mov.b64 {%0, %1}, %2;" : "=f"(r.x), "=f"(r.y) : "l"(v)); return r;
}

__device__ __forceinline__ float sigf(float x) {
    return 1.0f / (1.0f + __expf(-x));
}
__device__ __forceinline__ float tanh_f(float x) {
    // overflow-safe tanh via exp of -2|x|
    float t = __expf(-2.0f * fabsf(x));
    float y = (1.0f - t) / (1.0f + t);
    return copysignf(y, x);
}

// ======================================================================
// K1: m = h_in @ W  (per-layer 64x64 weight), also zeroes g_agg rows.
// One thread per node; W broadcast from smem; packed f32x2 FMA.
// ======================================================================
__global__ void __launch_bounds__(128) k_transform(
    const float* __restrict__ x, const float* __restrict__ W, int first)
{
    __shared__ __align__(16) float Ws[DIM * DIM];
    int tid = threadIdx.x;
    #pragma unroll
    for (int i = tid; i < DIM * DIM / 4; i += 128)
        ((float4*)Ws)[i] = __ldg(((const float4*)W) + i);
    __syncthreads();

    int n = blockIdx.x * 128 + tid;
    if (n >= NNODES) return;

    const float* hin = first ? x : g_h;

    ull acc[32];
    #pragma unroll
    for (int i = 0; i < 32; i++) acc[i] = 0ULL;   // bits of (0.f, 0.f)

    const float4* hr = (const float4*)(hin + (size_t)n * DIM);
    #pragma unroll 4
    for (int kk = 0; kk < 16; kk++) {
        float4 hv = __ldg(hr + kk);
        float hvals[4] = {hv.x, hv.y, hv.z, hv.w};
        #pragma unroll
        for (int u = 0; u < 4; u++) {
            int k = kk * 4 + u;
            ull hx = pack2(hvals[u], hvals[u]);
            const ulonglong2* wrow = (const ulonglong2*)(Ws + k * DIM);
            #pragma unroll
            for (int j = 0; j < 16; j++) {
                ulonglong2 w = wrow[j];           // W[k][4j..4j+3], broadcast LDS
                fma2(acc[2 * j],     hx, w.x);
                fma2(acc[2 * j + 1], hx, w.y);
            }
        }
    }

    float4* mout = (float4*)(g_m + (size_t)n * DIM);
    float4* aout = (float4*)(g_agg + (size_t)n * DIM);
    #pragma unroll
    for (int j = 0; j < 16; j++) {
        float2 a = unpack2(acc[2 * j]);
        float2 b = unpack2(acc[2 * j + 1]);
        mout[j] = make_float4(a.x, a.y, b.x, b.y);
        aout[j] = make_float4(0.f, 0.f, 0.f, 0.f);
    }
}

// ======================================================================
// K2: agg[dst] += m[src] over all edges. 16 threads per edge, float4
// payload, red.global.add.v4.f32 (no return trip, 4x fewer lane-ops).
// m and agg both L2-resident (12.8 MB each).
// NOTE: edge_index arrives as int32 (JAX x64 disabled downgrades the
// declared int64), so indices are read as const int*.
// ======================================================================
__global__ void __launch_bounds__(256) k_scatter(
    const int* __restrict__ src, const int* __restrict__ dst)
{
    int t = blockIdx.x * 256 + threadIdx.x;
    int e = t >> 4;
    int p = t & 15;
    if (e >= NEDGES) return;
    int s = __ldg(src + e);
    int d = __ldg(dst + e);
    float4 v = __ldg((const float4*)(g_m + (size_t)s * DIM) + p);
    float* a = g_agg + (size_t)d * DIM + (size_t)p * 4;
    asm volatile("red.global.add.v4.f32 [%0], {%1, %2, %3, %4};"
                 :: "l"(a), "f"(v.x), "f"(v.y), "f"(v.z), "f"(v.w)
                 : "memory");
}

// ======================================================================
// K3: GRU cell. 4 threads per node, each owns 16 output columns.
// Transposed weights in smem with +4-float padding per 16-column chunk
// (conflict-free LDS.128); node rows staged with stride-65 padding.
// All matmul math in packed fma.rn.f32x2.
// ======================================================================
#define WPAD 240   // 192 cols -> 12 chunks of 16, each padded by 4
#define RPAD 65
#define SMEM_GRU ((2 * 64 * WPAD + 2 * 64 * RPAD + 2 * 192) * 4)

__global__ void __launch_bounds__(256) k_gru(
    const float* __restrict__ x,
    const float* __restrict__ wih, const float* __restrict__ whh,
    const float* __restrict__ bih, const float* __restrict__ bhh,
    float* __restrict__ dout, int first, int last)
{
    extern __shared__ __align__(16) float sm[];
    float* wiT = sm;                    // [64][WPAD]
    float* whT = wiT + 64 * WPAD;       // [64][WPAD]
    float* ms  = whT + 64 * WPAD;       // [64][RPAD]
    float* hs  = ms + 64 * RPAD;        // [64][RPAD]
    float* bi  = hs + 64 * RPAD;        // [192]
    float* bh  = bi + 192;              // [192]

    int tid = threadIdx.x;
    const float* hin = first ? x : g_h;
    float* hout = last ? dout : g_h;

    // Transpose + pad weights into smem: wT[k][pad(j)] = w[j][k]
    for (int i = tid; i < 192 * 64; i += 256) {
        int j = i >> 6, k = i & 63;
        int jp = j + (j >> 4) * 4;
        wiT[k * WPAD + jp] = __ldg(wih + i);
        whT[k * WPAD + jp] = __ldg(whh + i);
    }
    if (tid < 192) { bi[tid] = __ldg(bih + tid); bh[tid] = __ldg(bhh + tid); }

    // Stage this block's 64 node rows (agg and h), coalesced reads
    int nbase = blockIdx.x * 64;
    for (int i = tid; i < 64 * DIM; i += 256) {
        int nl = i >> 6, k = i & 63;
        int n = nbase + nl;
        float mv = 0.f, hv = 0.f;
        if (n < NNODES) {
            mv = __ldg(g_agg + (size_t)n * DIM + k);
            hv = __ldg(hin + (size_t)n * DIM + k);
        }
        ms[nl * RPAD + k] = mv;
        hs[nl * RPAD + k] = hv;
    }
    __syncthreads();

    int nl = tid >> 2;     // local node 0..63
    int jc = tid & 3;      // column chunk: owns columns jc*16 .. jc*16+15
    int n = nbase + nl;

    // acc[0..2] = gi gates (r,z,n), acc[3..5] = gh gates; 8 f32x2 each
    ull acc[6][8];
    #pragma unroll
    for (int g = 0; g < 3; g++) {
        #pragma unroll
        for (int u = 0; u < 8; u++) {
            int j = g * 64 + jc * 16 + 2 * u;
            acc[g][u]     = pack2(bi[j], bi[j + 1]);
            acc[3 + g][u] = pack2(bh[j], bh[j + 1]);
        }
    }

    const float* wibase = wiT + jc * 20;   // chunk (g*4+jc) @ offset (g*4+jc)*20 floats
    const float* whbase = whT + jc * 20;

    #pragma unroll 4
    for (int k = 0; k < 64; k++) {
        float mk = ms[nl * RPAD + k];
        float hk = hs[nl * RPAD + k];
        ull m2 = pack2(mk, mk);
        ull h2 = pack2(hk, hk);
        const ulonglong2* wi = (const ulonglong2*)(wibase + k * WPAD);
        const ulonglong2* wh = (const ulonglong2*)(whbase + k * WPAD);
        #pragma unroll
        for (int g = 0; g < 3; g++) {
            #pragma unroll
            for (int q = 0; q < 4; q++) {
                ulonglong2 a = wi[g * 20 + q];   // 16B = 2 packed pairs
                ulonglong2 b = wh[g * 20 + q];
                fma2(acc[g][2 * q],         m2, a.x);
                fma2(acc[g][2 * q + 1],     m2, a.y);
                fma2(acc[3 + g][2 * q],     h2, b.x);
                fma2(acc[3 + g][2 * q + 1], h2, b.y);
            }
        }
    }

    if (n < NNODES) {
        float4 out[4];
        #pragma unroll
        for (int q = 0; q < 8; q++) {
            float2 ir = unpack2(acc[0][q]);
            float2 iz = unpack2(acc[1][q]);
            float2 in = unpack2(acc[2][q]);
            float2 hr = unpack2(acc[3][q]);
            float2 hz = unpack2(acc[4][q]);
            float2 hn = unpack2(acc[5][q]);
            int j = jc * 16 + 2 * q;
            float h0 = hs[nl * RPAD + j];
            float h1 = hs[nl * RPAD + j + 1];
            float r0 = sigf(ir.x + hr.x), r1 = sigf(ir.y + hr.y);
            float z0 = sigf(iz.x + hz.x), z1 = sigf(iz.y + hz.y);
            float n0 = tanh_f(in.x + r0 * hn.x), n1 = tanh_f(in.y + r1 * hn.y);
            float o0 = (1.0f - z0) * n0 + z0 * h0;
            float o1 = (1.0f - z1) * n1 + z1 * h1;
            ((float*)out)[2 * q]     = o0;
            ((float*)out)[2 * q + 1] = o1;
        }
        float4* op = (float4*)(hout + (size_t)n * DIM + jc * 16);
        #pragma unroll
        for (int q = 0; q < 4; q++) op[q] = out[q];
    }
}

// ======================================================================
extern "C" void kernel_launch(void* const* d_in, const int* in_sizes, int n_in,
                              void* d_out, int out_size)
{
    const float* x   = (const float*)d_in[0];
    const int*   ei  = (const int*)d_in[1];     // int32 (JAX x64 disabled)
    const float* W   = (const float*)d_in[2];
    const float* wih = (const float*)d_in[3];
    const float* whh = (const float*)d_in[4];
    const float* bih = (const float*)d_in[5];
    const float* bhh = (const float*)d_in[6];
    float*       out = (float*)d_out;

    const int* src = ei;
    const int* dst = ei + NEDGES;

    static int smem_set = 0;
    if (!smem_set) {
        cudaFuncSetAttribute(k_gru, cudaFuncAttributeMaxDynamicSharedMemorySize, SMEM_GRU);
        smem_set = 1;
    }

    const int g_tr = (NNODES + 127) / 128;           // 391
    const int g_sc = (NEDGES * 16) / 256;            // 50000 (exact)
    const int g_gr = (NNODES + 63) / 64;             // 782

    for (int l = 0; l < NSTEPS; l++) {
        int first = (l == 0);
        int last  = (l == NSTEPS - 1);
        k_transform<<<g_tr, 128>>>(x, W + (size_t)l * DIM * DIM, first);
        k_scatter<<<g_sc, 256>>>(src, dst);
        k_gru<<<g_gr, 256, SMEM_GRU>>>(x, wih, whh, bih, bhh, out, first, last);
    }
}